// round 5
// baseline (speedup 1.0000x reference)
#include <cuda_runtime.h>

#define NN 50000
#define NE 800000
#define ET (NE + NN)

// ---------------- scratch (device globals: no allocation allowed) ----------------
__device__ int   g_deg[NN];
__device__ int   g_starts[NN + 1];
__device__ int   g_cursor[NN];
__device__ int   g_ssrc[ET];          // src ids sorted by dst (CSR payload)
__device__ float g_xl[NN * 128];      // x @ Wl  (H*dout = 128)
__device__ float g_xr[NN * 128];      // x @ Wr
__device__ float g_y[NN * 64];        // pre-norm layer output
__device__ float g_xn[NN * 64];       // post-norm layer output (next layer input)
__device__ float g_sums[128];         // [0:64) sum(y), [64:128) sum(y^2)

__device__ __forceinline__ float lrelu(float v) { return v > 0.f ? v : 0.2f * v; }

// ---------------- CSR build (once per call, reused for all 3 layers) -------------
__global__ void k_zero_deg() {
    int i = blockIdx.x * blockDim.x + threadIdx.x;
    if (i < NN) g_deg[i] = 0;
}

__global__ void k_zero_sums() {
    if (threadIdx.x < 128) g_sums[threadIdx.x] = 0.f;
}

__global__ void k_count(const int* __restrict__ ei) {
    int e = blockIdx.x * blockDim.x + threadIdx.x;
    if (e >= ET) return;
    int d = (e < NE) ? ei[NE + e] : (e - NE);   // self-loop for e >= NE
    atomicAdd(&g_deg[d], 1);
}

__global__ void k_scan() {
    __shared__ int sm[1024];
    int t = threadIdx.x;
    const int per = (NN + 1023) / 1024;   // 49
    int lo = t * per; if (lo > NN) lo = NN;
    int hi = lo + per; if (hi > NN) hi = NN;
    int s = 0;
    for (int i = lo; i < hi; i++) s += g_deg[i];
    sm[t] = s;
    __syncthreads();
    for (int o = 1; o < 1024; o <<= 1) {
        int v = (t >= o) ? sm[t - o] : 0;
        __syncthreads();
        sm[t] += v;
        __syncthreads();
    }
    int off = (t > 0) ? sm[t - 1] : 0;
    for (int i = lo; i < hi; i++) {
        int dg = g_deg[i];
        g_starts[i] = off;
        g_cursor[i] = off;
        off += dg;
    }
    if (t == 1023) g_starts[NN] = sm[1023];
}

__global__ void k_scatter(const int* __restrict__ ei) {
    int e = blockIdx.x * blockDim.x + threadIdx.x;
    if (e >= ET) return;
    int s, d;
    if (e < NE) { s = ei[e]; d = ei[NE + e]; }
    else        { s = e - NE; d = e - NE; }
    int pos = atomicAdd(&g_cursor[d], 1);
    g_ssrc[pos] = s;
}

// ---------------- x @ Wl, x @ Wr : warp per node, lane owns 4 output cols --------
__global__ void k_gemm(const float* __restrict__ xext,
                       const float* __restrict__ Wl,
                       const float* __restrict__ Wr,
                       int din, int use_internal) {
    int w = (blockIdx.x * blockDim.x + threadIdx.x) >> 5;
    int lane = threadIdx.x & 31;
    if (w >= NN) return;
    const float* x = use_internal ? (const float*)g_xn : xext;

    float xv0 = (lane < din)      ? x[w * din + lane]      : 0.f;
    float xv1 = (lane + 32 < din) ? x[w * din + lane + 32] : 0.f;

    float4 al = make_float4(0.f, 0.f, 0.f, 0.f);
    float4 ar = make_float4(0.f, 0.f, 0.f, 0.f);
    const float4* wl4 = (const float4*)Wl;
    const float4* wr4 = (const float4*)Wr;

#pragma unroll 4
    for (int k = 0; k < din; k++) {
        float xk = __shfl_sync(0xffffffffu, (k < 32) ? xv0 : xv1, k & 31);
        float4 wl = wl4[k * 32 + lane];
        float4 wr = wr4[k * 32 + lane];
        al.x += xk * wl.x; al.y += xk * wl.y; al.z += xk * wl.z; al.w += xk * wl.w;
        ar.x += xk * wr.x; ar.y += xk * wr.y; ar.z += xk * wr.z; ar.w += xk * wr.w;
    }
    ((float4*)g_xl)[w * 32 + lane] = al;
    ((float4*)g_xr)[w * 32 + lane] = ar;
}

// ---------------- fused attention: warp per dst node, online softmax -------------
// lane l covers channels [4l, 4l+4); lanes 0-15 = head0, 16-31 = head1.
__global__ __launch_bounds__(512) void k_attn(const float* __restrict__ att,
                                              const float* __restrict__ bias) {
    __shared__ float ssum[128];
    int t = threadIdx.x;
    if (t < 128) ssum[t] = 0.f;
    __syncthreads();

    int w = (blockIdx.x * blockDim.x + t) >> 5;
    int lane = t & 31;

    if (w < NN) {
        int s = g_starts[w];
        int e1 = g_starts[w + 1];
        const float4* xl4 = (const float4*)g_xl;
        float4 xr = ((const float4*)g_xr)[w * 32 + lane];
        float4 av = ((const float4*)att)[lane];

        float m = -1e30f, z = 0.f;
        float4 acc = make_float4(0.f, 0.f, 0.f, 0.f);

        for (int e = s; e < e1; e++) {
            int src = g_ssrc[e];
            float4 xv = xl4[src * 32 + lane];
            float v = av.x * lrelu(xv.x + xr.x)
                    + av.y * lrelu(xv.y + xr.y)
                    + av.z * lrelu(xv.z + xr.z)
                    + av.w * lrelu(xv.w + xr.w);
            // half-warp reduce: lanes 0-15 -> head0 logit, 16-31 -> head1 logit
            v += __shfl_xor_sync(0xffffffffu, v, 8);
            v += __shfl_xor_sync(0xffffffffu, v, 4);
            v += __shfl_xor_sync(0xffffffffu, v, 2);
            v += __shfl_xor_sync(0xffffffffu, v, 1);

            if (v > m) {                 // online softmax rescale
                float sc = __expf(m - v);
                z = z * sc + 1.f;
                acc.x = acc.x * sc + xv.x;
                acc.y = acc.y * sc + xv.y;
                acc.z = acc.z * sc + xv.z;
                acc.w = acc.w * sc + xv.w;
                m = v;
            } else {
                float a = __expf(v - m);
                z += a;
                acc.x += a * xv.x;
                acc.y += a * xv.y;
                acc.z += a * xv.z;
                acc.w += a * xv.w;
            }
        }
        float inv = 1.f / z;
        acc.x *= inv; acc.y *= inv; acc.z *= inv; acc.w *= inv;

        // mean over the 2 heads: lane l (<16) combines with lane l+16
        float ox = acc.x + __shfl_down_sync(0xffffffffu, acc.x, 16);
        float oy = acc.y + __shfl_down_sync(0xffffffffu, acc.y, 16);
        float oz = acc.z + __shfl_down_sync(0xffffffffu, acc.z, 16);
        float ow = acc.w + __shfl_down_sync(0xffffffffu, acc.w, 16);

        if (lane < 16) {
            float4 bv = ((const float4*)bias)[lane];
            float4 y;
            y.x = 0.5f * ox + bv.x;
            y.y = 0.5f * oy + bv.y;
            y.z = 0.5f * oz + bv.z;
            y.w = 0.5f * ow + bv.w;
            ((float4*)g_y)[w * 16 + lane] = y;
            int c = lane * 4;
            atomicAdd(&ssum[c + 0], y.x);
            atomicAdd(&ssum[c + 1], y.y);
            atomicAdd(&ssum[c + 2], y.z);
            atomicAdd(&ssum[c + 3], y.w);
            atomicAdd(&ssum[64 + c + 0], y.x * y.x);
            atomicAdd(&ssum[64 + c + 1], y.y * y.y);
            atomicAdd(&ssum[64 + c + 2], y.z * y.z);
            atomicAdd(&ssum[64 + c + 3], y.w * y.w);
        }
    }
    __syncthreads();
    if (t < 128) atomicAdd(&g_sums[t], ssum[t]);
}

// ---------------- graph norm + relu ----------------------------------------------
// var = E[y^2] - mu^2 * (2g - g^2)  with mu = E[y]  (o = y - g*mu)
__global__ void k_norm(const float* __restrict__ gw,
                       const float* __restrict__ gb,
                       const float* __restrict__ gm,
                       float* __restrict__ outp, int to_internal) {
    int i = blockIdx.x * blockDim.x + threadIdx.x;
    if (i >= NN * 64) return;
    int c = i & 63;
    float g  = gm[c];
    float mu = g_sums[c] * (1.f / NN);
    float var = g_sums[64 + c] * (1.f / NN) - mu * mu * (2.f * g - g * g);
    float r = rsqrtf(var + 1e-5f);
    float o = g_y[i] - g * mu;
    float res = gw[c] * o * r + gb[c];
    res = fmaxf(res, 0.f);
    if (to_internal) g_xn[i] = res;
    else             outp[i] = res;
}

// ---------------- launch ----------------------------------------------------------
extern "C" void kernel_launch(void* const* d_in, const int* in_sizes, int n_in,
                              void* d_out, int out_size) {
    const float* x  = (const float*)d_in[0];
    const int*   ei = (const int*)d_in[1];
    const float *Wl[3], *Wr[3], *att[3], *b[3], *gw[3], *gb[3], *gm[3];
    for (int i = 0; i < 3; i++) {
        int base = 2 + 7 * i;
        Wl[i]  = (const float*)d_in[base + 0];
        Wr[i]  = (const float*)d_in[base + 1];
        att[i] = (const float*)d_in[base + 2];
        b[i]   = (const float*)d_in[base + 3];
        gw[i]  = (const float*)d_in[base + 4];
        gb[i]  = (const float*)d_in[base + 5];
        gm[i]  = (const float*)d_in[base + 6];
    }
    float* out = (float*)d_out;

    // CSR build (shared by all 3 layers)
    k_zero_deg<<<(NN + 255) / 256, 256>>>();
    k_count<<<(ET + 255) / 256, 256>>>(ei);
    k_scan<<<1, 1024>>>();
    k_scatter<<<(ET + 255) / 256, 256>>>(ei);

    int din = 3;
    for (int l = 0; l < 3; l++) {
        int use_internal = (l > 0) ? 1 : 0;
        k_gemm<<<(NN * 32 + 255) / 256, 256>>>(x, Wl[l], Wr[l], din, use_internal);
        k_zero_sums<<<1, 128>>>();
        k_attn<<<(NN + 15) / 16, 512>>>(att[l], b[l]);
        k_norm<<<(NN * 64 + 255) / 256, 256>>>(gw[l], gb[l], gm[l], out,
                                               (l == 2) ? 0 : 1);
        din = 64;
    }
}